// round 1
// baseline (speedup 1.0000x reference)
#include <cuda_runtime.h>
#include <math.h>

#define NDEST 8192
#define NSRC  8192
#define FEATD 1024
#define TFD   256
#define EMB   64
#define HID   128
#define HEADS 2

// scratch (static device arrays: allocation-free)
__device__ float g_transformed[(size_t)NSRC * TFD];          // 8 MB
__device__ float g_hsrc[(size_t)HEADS * NSRC * HID];         // 8 MB
__device__ float g_q[(size_t)HEADS * NDEST * HID];           // 8 MB
__device__ float g_wc[HEADS * EMB * HID];                    // 64 KB

// ---------------------------------------------------------------------------
// SGEMM: C[M,N] = A[M,K] @ op(B) (+ bias), 64x64 tile, BK=16, 256 threads,
// 4x4 per-thread microtile. BT=true: B stored [N,K] (i.e. C = A @ B^T).
// Optional batching over blockIdx.z with strides on B and C (A shared).
// All dims assumed multiples of tile sizes (true for this problem).
// ---------------------------------------------------------------------------
template<bool BT, bool HASBIAS>
__global__ __launch_bounds__(256) void sgemm_k(
    const float* __restrict__ A, const float* __restrict__ B,
    const float* __restrict__ bias, float* __restrict__ C,
    int M, int N, int K, long long strideB, long long strideC)
{
  const float* Bp = B + (size_t)blockIdx.z * strideB;
  float* Cp = C + (size_t)blockIdx.z * strideC;

  __shared__ float As[16][68];
  __shared__ float Bs[16][68];

  const int t  = threadIdx.x;
  const int tx = t & 15;
  const int ty = t >> 4;
  const int row0 = blockIdx.y << 6;
  const int col0 = blockIdx.x << 6;

  const int aRow = t >> 2;        // 0..63
  const int aK   = (t & 3) << 2;  // 0,4,8,12
  const int bK   = t >> 4;        // 0..15
  const int bN   = (t & 15) << 2; // 0..60

  float acc[4][4] = {};

  for (int k0 = 0; k0 < K; k0 += 16) {
    float4 a4 = *(const float4*)(A + (size_t)(row0 + aRow) * K + (k0 + aK));
    As[aK+0][aRow] = a4.x; As[aK+1][aRow] = a4.y;
    As[aK+2][aRow] = a4.z; As[aK+3][aRow] = a4.w;
    if (BT) {
      float4 b4 = *(const float4*)(Bp + (size_t)(col0 + aRow) * K + (k0 + aK));
      Bs[aK+0][aRow] = b4.x; Bs[aK+1][aRow] = b4.y;
      Bs[aK+2][aRow] = b4.z; Bs[aK+3][aRow] = b4.w;
    } else {
      float4 b4 = *(const float4*)(Bp + (size_t)(k0 + bK) * N + (col0 + bN));
      *(float4*)&Bs[bK][bN] = b4;
    }
    __syncthreads();
    #pragma unroll
    for (int k = 0; k < 16; k++) {
      float4 a = *(const float4*)&As[k][ty << 2];
      float4 b = *(const float4*)&Bs[k][tx << 2];
      acc[0][0] += a.x*b.x; acc[0][1] += a.x*b.y; acc[0][2] += a.x*b.z; acc[0][3] += a.x*b.w;
      acc[1][0] += a.y*b.x; acc[1][1] += a.y*b.y; acc[1][2] += a.y*b.z; acc[1][3] += a.y*b.w;
      acc[2][0] += a.z*b.x; acc[2][1] += a.z*b.y; acc[2][2] += a.z*b.z; acc[2][3] += a.z*b.w;
      acc[3][0] += a.w*b.x; acc[3][1] += a.w*b.y; acc[3][2] += a.w*b.z; acc[3][3] += a.w*b.w;
    }
    __syncthreads();
  }

  float4 bv = make_float4(0.f, 0.f, 0.f, 0.f);
  if (HASBIAS) bv = *(const float4*)(bias + col0 + (tx << 2));
  #pragma unroll
  for (int i = 0; i < 4; i++) {
    float4 o = make_float4(acc[i][0]+bv.x, acc[i][1]+bv.y, acc[i][2]+bv.z, acc[i][3]+bv.w);
    *(float4*)(Cp + (size_t)(row0 + (ty<<2) + i) * N + (col0 + (tx<<2))) = o;
  }
}

// ---------------------------------------------------------------------------
// Wc[h] = att_W[h] (64x128) @ att_W2[h] (128x128)  -> [2][64][128]
// ---------------------------------------------------------------------------
__global__ void wc_kernel(const float* __restrict__ attW,
                          const float* __restrict__ attW2,
                          float* __restrict__ wc)
{
  int h = blockIdx.y;
  int idx = blockIdx.x * blockDim.x + threadIdx.x;   // 0..8191
  int e = idx >> 7, d = idx & 127;
  const float* W  = attW  + h * EMB * HID + e * HID;
  const float* W2 = attW2 + h * HID * HID;
  float s = 0.f;
  #pragma unroll 8
  for (int k = 0; k < HID; k++) s += W[k] * W2[k * HID + d];
  wc[h * EMB * HID + idx] = s;
}

// ---------------------------------------------------------------------------
// Sparse masked attention, one block per destination row m.
// scores only where bias>0 (exact: exp(NEG_INF - max) == 0 in the reference).
// No max-subtraction needed: elu scores are O(1), softmax shift-invariant.
// w[n] = 0.5*(e0/Z0 + e1/Z1); out[m,:] = sum_n w[n] * transformed[n,:].
// ---------------------------------------------------------------------------
__device__ __forceinline__ float2 score_exp_pair(
    int n, const float* qsh, const float* __restrict__ hsrc, int lane)
{
  const float4* k0 = (const float4*)(hsrc + (size_t)n * HID);
  const float4* k1 = (const float4*)(hsrc + ((size_t)NSRC + n) * HID);
  const float4 a0 = ((const float4*)qsh)[lane];
  const float4 a1 = ((const float4*)qsh)[32 + lane];
  float4 b0 = k0[lane], b1 = k1[lane];
  float s0 = a0.x*b0.x + a0.y*b0.y + a0.z*b0.z + a0.w*b0.w;
  float s1 = a1.x*b1.x + a1.y*b1.y + a1.z*b1.z + a1.w*b1.w;
  #pragma unroll
  for (int o = 16; o; o >>= 1) {
    s0 += __shfl_xor_sync(0xffffffffu, s0, o);
    s1 += __shfl_xor_sync(0xffffffffu, s1, o);
  }
  float e0 = expf(s0 > 0.f ? s0 : expm1f(s0));  // exp(elu(s))
  float e1 = expf(s1 > 0.f ? s1 : expm1f(s1));
  return make_float2(e0, e1);
}

#define SC_CHUNK 2048

__global__ __launch_bounds__(256) void attn_kernel(
    const float* __restrict__ bias,
    const float* __restrict__ q,            // [2][NDEST][HID]
    const float* __restrict__ hsrc,         // [2][NSRC][HID]
    const float* __restrict__ transformed,  // [NSRC][TFD]
    float* __restrict__ out)                // [NDEST][TFD]
{
  const int m = blockIdx.x;
  const int t = threadIdx.x;                 // 256 threads
  const int warp = t >> 5, lane = t & 31;

  __shared__ unsigned short sidx[NSRC];      // 16 KB: nonzero column indices
  __shared__ __align__(16) float qsh[2 * HID];
  __shared__ float scw[SC_CHUNK];            // 8 KB: per-chunk combined weights
  __shared__ int  s_scan[256];
  __shared__ float red[16];
  __shared__ float sZ0, sZ1;

  // load q rows for this m (both heads)
  {
    int h = t >> 7, d = t & 127;
    qsh[t] = q[((size_t)h * NDEST + m) * HID + d];
  }

  // --- compact nonzero bias columns (deterministic, sorted order) ---
  const float4* brow4 = (const float4*)(bias + (size_t)m * NSRC);
  int cnt = 0;
  #pragma unroll
  for (int i = 0; i < 8; i++) {
    float4 v = brow4[t * 8 + i];
    cnt += (v.x > 0.f) + (v.y > 0.f) + (v.z > 0.f) + (v.w > 0.f);
  }
  s_scan[t] = cnt;
  __syncthreads();
  for (int off = 1; off < 256; off <<= 1) {
    int add = (t >= off) ? s_scan[t - off] : 0;
    __syncthreads();
    s_scan[t] += add;
    __syncthreads();
  }
  const int nnz = s_scan[255];
  int base = s_scan[t] - cnt;
  #pragma unroll
  for (int i = 0; i < 8; i++) {
    float4 v = brow4[t * 8 + i];
    int b0 = t * 32 + i * 4;
    if (v.x > 0.f) sidx[base++] = (unsigned short)(b0 + 0);
    if (v.y > 0.f) sidx[base++] = (unsigned short)(b0 + 1);
    if (v.z > 0.f) sidx[base++] = (unsigned short)(b0 + 2);
    if (v.w > 0.f) sidx[base++] = (unsigned short)(b0 + 3);
  }
  __syncthreads();

  if (nnz == 0) {
    // all masked: softmax is uniform over all 8192 sources (reference behavior)
    float acc = 0.f;
    for (int n = 0; n < NSRC; n++) acc += transformed[(size_t)n * TFD + t];
    out[(size_t)m * TFD + t] = acc * (1.0f / NSRC);
    return;
  }

  // --- phase 1: softmax denominators per head ---
  float pZ0 = 0.f, pZ1 = 0.f;
  for (int j = warp; j < nnz; j += 8) {
    float2 e = score_exp_pair(sidx[j], qsh, hsrc, lane);
    pZ0 += e.x; pZ1 += e.y;
  }
  if (lane == 0) { red[warp] = pZ0; red[8 + warp] = pZ1; }
  __syncthreads();
  if (t == 0) {
    float z0 = 0.f, z1 = 0.f;
    #pragma unroll
    for (int w = 0; w < 8; w++) { z0 += red[w]; z1 += red[8 + w]; }
    sZ0 = z0; sZ1 = z1;
  }
  __syncthreads();
  const float inv0 = 0.5f / sZ0;
  const float inv1 = 0.5f / sZ1;

  // --- phase 2: recompute weights per chunk, gather-accumulate ---
  float acc = 0.f;
  for (int c0 = 0; c0 < nnz; c0 += SC_CHUNK) {
    int cend = min(nnz, c0 + SC_CHUNK);
    for (int j = c0 + warp; j < cend; j += 8) {
      float2 e = score_exp_pair(sidx[j], qsh, hsrc, lane);
      if (lane == 0) scw[j - c0] = e.x * inv0 + e.y * inv1;
    }
    __syncthreads();
    int cs = cend - c0;
    #pragma unroll 4
    for (int j = 0; j < cs; j++)
      acc += scw[j] * transformed[(size_t)sidx[c0 + j] * TFD + t];
    __syncthreads();
  }
  out[(size_t)m * TFD + t] = acc;
}

// ---------------------------------------------------------------------------
extern "C" void kernel_launch(void* const* d_in, const int* in_sizes, int n_in,
                              void* d_out, int out_size)
{
  const float* bias        = (const float*)d_in[0];
  const float* emb_dest    = (const float*)d_in[1];
  const float* emb_src     = (const float*)d_in[2];
  const float* feature_src = (const float*)d_in[3];
  const float* fc_W        = (const float*)d_in[4];
  const float* fc_b        = (const float*)d_in[5];
  const float* dec_W       = (const float*)d_in[6];
  const float* dec_b       = (const float*)d_in[7];
  const float* att_W       = (const float*)d_in[8];
  const float* att_W2      = (const float*)d_in[9];

  float* out_re  = (float*)d_out;
  float* out_hat = out_re + (size_t)NDEST * TFD;

  float *transformed, *hsrc, *qp, *wc;
  cudaGetSymbolAddress((void**)&transformed, g_transformed);
  cudaGetSymbolAddress((void**)&hsrc, g_hsrc);
  cudaGetSymbolAddress((void**)&qp, g_q);
  cudaGetSymbolAddress((void**)&wc, g_wc);

  // Wc[h] = att_W[h] @ att_W2[h]
  wc_kernel<<<dim3(32, 2), 256>>>(att_W, att_W2, wc);

  // h_src[h] = emb_src @ att_W[h]   ([8192,64] @ [64,128])
  sgemm_k<false, false><<<dim3(HID / 64, NSRC / 64, HEADS), 256>>>(
      emb_src, att_W, nullptr, hsrc, NSRC, HID, EMB,
      (long long)EMB * HID, (long long)NSRC * HID);

  // q[h] = emb_dest @ Wc[h]
  sgemm_k<false, false><<<dim3(HID / 64, NDEST / 64, HEADS), 256>>>(
      emb_dest, wc, nullptr, qp, NDEST, HID, EMB,
      (long long)EMB * HID, (long long)NDEST * HID);

  // transformed = feature_src @ fc_W^T + fc_b   ([8192,1024] @ [1024,256])
  sgemm_k<true, true><<<dim3(TFD / 64, NSRC / 64, 1), 256>>>(
      feature_src, fc_W, fc_b, transformed, NSRC, TFD, FEATD, 0, 0);

  // feature_hat = transformed @ dec_W^T + dec_b   ([8192,256] @ [256,1024])
  sgemm_k<true, true><<<dim3(FEATD / 64, NSRC / 64, 1), 256>>>(
      transformed, dec_W, dec_b, out_hat, NSRC, FEATD, TFD, 0, 0);

  // sparse masked attention + aggregation
  attn_kernel<<<NDEST, 256>>>(bias, qp, hsrc, transformed, out_re);
}

// round 3
// speedup vs baseline: 1.5397x; 1.5397x over previous
#include <cuda_runtime.h>
#include <math.h>
#include <stdint.h>

#define NDEST 8192
#define NSRC  8192
#define FEATD 1024
#define TFD   256
#define EMB   64
#define HID   128
#define HEADS 2

// scratch (static device arrays: allocation-free)
__device__ float g_transformed[(size_t)NSRC * TFD];          // 8 MB
__device__ float g_hsrc[(size_t)HEADS * NSRC * HID];         // 8 MB
__device__ float g_q[(size_t)HEADS * NDEST * HID];           // 8 MB
__device__ float g_wc[HEADS * EMB * HID];                    // 64 KB

// ===========================================================================
// TF32 tensor-core GEMM:  C[M,N] = A[M,K] @ B[N,K]^T (+ bias[N])
// BM=128, BN=64, BK=32, 256 threads (8 warps as 4m x 2n, warp tile 32x32).
// Register double-buffered global->smem; k-permuted smem layout so every
// mma fragment load is one conflict-free LDS.64 (row stride 40 words).
// Requires M%128==0, N%64==0, K%32==0 (true for all uses here).
// ===========================================================================
__device__ __forceinline__ uint32_t f2tf(float f) {
  uint32_t u;
  asm("cvt.rna.tf32.f32 %0, %1;" : "=r"(u) : "f"(f));
  return u;
}

// store 8 k-consecutive values permuted: offsets (2j)->k=j, (2j+1)->k=j+4
__device__ __forceinline__ void store_perm(uint32_t* p, float4 lo, float4 hi) {
  uint4 u0 = make_uint4(f2tf(lo.x), f2tf(hi.x), f2tf(lo.y), f2tf(hi.y));
  uint4 u1 = make_uint4(f2tf(lo.z), f2tf(hi.z), f2tf(lo.w), f2tf(hi.w));
  *(uint4*)p = u0;
  *(uint4*)(p + 4) = u1;
}

__device__ __forceinline__ void mma_tf32(float* d, const uint32_t* a, uint2 b) {
  asm volatile(
      "mma.sync.aligned.m16n8k8.row.col.f32.tf32.tf32.f32 "
      "{%0,%1,%2,%3}, {%4,%5,%6,%7}, {%8,%9}, {%0,%1,%2,%3};\n"
      : "+f"(d[0]), "+f"(d[1]), "+f"(d[2]), "+f"(d[3])
      : "r"(a[0]), "r"(a[1]), "r"(a[2]), "r"(a[3]), "r"(b.x), "r"(b.y));
}

__global__ __launch_bounds__(256) void tf32gemm_k(
    const float* __restrict__ A, const float* __restrict__ B,
    const float* __restrict__ bias, float* __restrict__ C,
    int M, int N, int K)
{
  __shared__ uint32_t As[128][40];
  __shared__ uint32_t Bs[64][40];

  const int t = threadIdx.x;
  const int lane = t & 31, w = t >> 5;
  const int wm = (w & 3) * 32;
  const int wn = (w >> 2) * 32;
  const int g = lane >> 2, c = lane & 3;

  const int row0 = blockIdx.y * 128;
  const int col0 = blockIdx.x * 64;

  const int lr = t >> 2;        // 0..63
  const int lk = (t & 3) * 8;   // 0,8,16,24

  const float* pA0 = A + (size_t)(row0 + lr) * K + lk;
  const float* pA1 = A + (size_t)(row0 + lr + 64) * K + lk;
  const float* pB  = B + (size_t)(col0 + lr) * K + lk;

  float4 a0lo = *(const float4*)(pA0);
  float4 a0hi = *(const float4*)(pA0 + 4);
  float4 a1lo = *(const float4*)(pA1);
  float4 a1hi = *(const float4*)(pA1 + 4);
  float4 blo  = *(const float4*)(pB);
  float4 bhi  = *(const float4*)(pB + 4);

  float acc[2][4][4] = {};

  for (int k0 = 0; k0 < K; k0 += 32) {
    store_perm(&As[lr][lk],      a0lo, a0hi);
    store_perm(&As[lr + 64][lk], a1lo, a1hi);
    store_perm(&Bs[lr][lk],      blo,  bhi);
    __syncthreads();

    if (k0 + 32 < K) {
      a0lo = *(const float4*)(pA0 + k0 + 32);
      a0hi = *(const float4*)(pA0 + k0 + 36);
      a1lo = *(const float4*)(pA1 + k0 + 32);
      a1hi = *(const float4*)(pA1 + k0 + 36);
      blo  = *(const float4*)(pB + k0 + 32);
      bhi  = *(const float4*)(pB + k0 + 36);
    }

    #pragma unroll
    for (int ks = 0; ks < 4; ks++) {
      uint32_t af[2][4];
      uint2 bf[4];
      #pragma unroll
      for (int mi = 0; mi < 2; mi++) {
        uint2 lo = *(uint2*)&As[wm + mi * 16 + g][ks * 8 + 2 * c];
        uint2 hi = *(uint2*)&As[wm + mi * 16 + g + 8][ks * 8 + 2 * c];
        af[mi][0] = lo.x; af[mi][1] = hi.x; af[mi][2] = lo.y; af[mi][3] = hi.y;
      }
      #pragma unroll
      for (int ni = 0; ni < 4; ni++)
        bf[ni] = *(uint2*)&Bs[wn + ni * 8 + g][ks * 8 + 2 * c];
      #pragma unroll
      for (int mi = 0; mi < 2; mi++)
        #pragma unroll
        for (int ni = 0; ni < 4; ni++)
          mma_tf32(acc[mi][ni], af[mi], bf[ni]);
    }
    __syncthreads();
  }

  #pragma unroll
  for (int mi = 0; mi < 2; mi++) {
    int r = row0 + wm + mi * 16 + g;
    #pragma unroll
    for (int ni = 0; ni < 4; ni++) {
      int cc = col0 + wn + ni * 8 + 2 * c;
      float2 bv = *(const float2*)(bias + cc);
      float* d = acc[mi][ni];
      *(float2*)(C + (size_t)r * N + cc) =
          make_float2(d[0] + bv.x, d[1] + bv.y);
      *(float2*)(C + (size_t)(r + 8) * N + cc) =
          make_float2(d[2] + bv.x, d[3] + bv.y);
    }
  }
}

// ---------------------------------------------------------------------------
// fp32 SGEMM for the small score-path projections (kept fp32 for accuracy).
// C[M,N] = A[M,K] @ B (+0), 64x64 tile, BK=16. Batched over blockIdx.z.
// ---------------------------------------------------------------------------
__global__ __launch_bounds__(256) void sgemm_k(
    const float* __restrict__ A, const float* __restrict__ B,
    float* __restrict__ C,
    int M, int N, int K, long long strideB, long long strideC)
{
  const float* Bp = B + (size_t)blockIdx.z * strideB;
  float* Cp = C + (size_t)blockIdx.z * strideC;

  __shared__ float As[16][68];
  __shared__ float Bs[16][68];

  const int t  = threadIdx.x;
  const int tx = t & 15;
  const int ty = t >> 4;
  const int row0 = blockIdx.y << 6;
  const int col0 = blockIdx.x << 6;

  const int aRow = t >> 2;
  const int aK   = (t & 3) << 2;
  const int bK   = t >> 4;
  const int bN   = (t & 15) << 2;

  float acc[4][4] = {};

  for (int k0 = 0; k0 < K; k0 += 16) {
    float4 a4 = *(const float4*)(A + (size_t)(row0 + aRow) * K + (k0 + aK));
    As[aK+0][aRow] = a4.x; As[aK+1][aRow] = a4.y;
    As[aK+2][aRow] = a4.z; As[aK+3][aRow] = a4.w;
    float4 b4 = *(const float4*)(Bp + (size_t)(k0 + bK) * N + (col0 + bN));
    *(float4*)&Bs[bK][bN] = b4;
    __syncthreads();
    #pragma unroll
    for (int k = 0; k < 16; k++) {
      float4 a = *(const float4*)&As[k][ty << 2];
      float4 b = *(const float4*)&Bs[k][tx << 2];
      acc[0][0] += a.x*b.x; acc[0][1] += a.x*b.y; acc[0][2] += a.x*b.z; acc[0][3] += a.x*b.w;
      acc[1][0] += a.y*b.x; acc[1][1] += a.y*b.y; acc[1][2] += a.y*b.z; acc[1][3] += a.y*b.w;
      acc[2][0] += a.z*b.x; acc[2][1] += a.z*b.y; acc[2][2] += a.z*b.z; acc[2][3] += a.z*b.w;
      acc[3][0] += a.w*b.x; acc[3][1] += a.w*b.y; acc[3][2] += a.w*b.z; acc[3][3] += a.w*b.w;
    }
    __syncthreads();
  }

  #pragma unroll
  for (int i = 0; i < 4; i++) {
    float4 o = make_float4(acc[i][0], acc[i][1], acc[i][2], acc[i][3]);
    *(float4*)(Cp + (size_t)(row0 + (ty<<2) + i) * N + (col0 + (tx<<2))) = o;
  }
}

// ---------------------------------------------------------------------------
// Wc[h] = att_W[h] (64x128) @ att_W2[h] (128x128)
// ---------------------------------------------------------------------------
__global__ void wc_kernel(const float* __restrict__ attW,
                          const float* __restrict__ attW2,
                          float* __restrict__ wc)
{
  int h = blockIdx.y;
  int idx = blockIdx.x * blockDim.x + threadIdx.x;
  int e = idx >> 7, d = idx & 127;
  const float* W  = attW  + h * EMB * HID + e * HID;
  const float* W2 = attW2 + h * HID * HID;
  float s = 0.f;
  #pragma unroll 8
  for (int k = 0; k < HID; k++) s += W[k] * W2[k * HID + d];
  wc[h * EMB * HID + idx] = s;
}

// ---------------------------------------------------------------------------
// Sparse masked attention, one block per destination row m.
// exp values cached in smem (ECAP covers nnz with ~12 sigma margin;
// correct fallback recompute path for the impossible overflow case).
// ---------------------------------------------------------------------------
__device__ __forceinline__ float2 score_exp_pair(
    int n, const float* qsh, const float* __restrict__ hsrc, int lane)
{
  const float4* k0 = (const float4*)(hsrc + (size_t)n * HID);
  const float4* k1 = (const float4*)(hsrc + ((size_t)NSRC + n) * HID);
  const float4 a0 = ((const float4*)qsh)[lane];
  const float4 a1 = ((const float4*)qsh)[32 + lane];
  float4 b0 = k0[lane], b1 = k1[lane];
  float s0 = a0.x*b0.x + a0.y*b0.y + a0.z*b0.z + a0.w*b0.w;
  float s1 = a1.x*b1.x + a1.y*b1.y + a1.z*b1.z + a1.w*b1.w;
  #pragma unroll
  for (int o = 16; o; o >>= 1) {
    s0 += __shfl_xor_sync(0xffffffffu, s0, o);
    s1 += __shfl_xor_sync(0xffffffffu, s1, o);
  }
  float e0 = expf(s0 > 0.f ? s0 : expm1f(s0));  // exp(elu(s))
  float e1 = expf(s1 > 0.f ? s1 : expm1f(s1));
  return make_float2(e0, e1);
}

#define ECAP 2048

__global__ __launch_bounds__(256) void attn_kernel(
    const float* __restrict__ bias,
    const float* __restrict__ q,            // [2][NDEST][HID]
    const float* __restrict__ hsrc,         // [2][NSRC][HID]
    const float* __restrict__ transformed,  // [NSRC][TFD]
    float* __restrict__ out)                // [NDEST][TFD]
{
  const int m = blockIdx.x;
  const int t = threadIdx.x;
  const int warp = t >> 5, lane = t & 31;

  __shared__ unsigned short sidx[NSRC];        // 16 KB
  __shared__ __align__(16) float qsh[2 * HID];
  __shared__ float2 ecache[ECAP];              // 16 KB
  __shared__ float scw[ECAP];                  // 8 KB
  __shared__ int  s_scan[256];
  __shared__ float red[16];
  __shared__ float sZ0, sZ1;

  {
    int h = t >> 7, d = t & 127;
    qsh[t] = q[((size_t)h * NDEST + m) * HID + d];
  }

  // compact nonzero bias columns (sorted order)
  const float4* brow4 = (const float4*)(bias + (size_t)m * NSRC);
  int cnt = 0;
  #pragma unroll
  for (int i = 0; i < 8; i++) {
    float4 v = brow4[t * 8 + i];
    cnt += (v.x > 0.f) + (v.y > 0.f) + (v.z > 0.f) + (v.w > 0.f);
  }
  s_scan[t] = cnt;
  __syncthreads();
  for (int off = 1; off < 256; off <<= 1) {
    int add = (t >= off) ? s_scan[t - off] : 0;
    __syncthreads();
    s_scan[t] += add;
    __syncthreads();
  }
  const int nnz = s_scan[255];
  int base = s_scan[t] - cnt;
  #pragma unroll
  for (int i = 0; i < 8; i++) {
    float4 v = brow4[t * 8 + i];
    int b0 = t * 32 + i * 4;
    if (v.x > 0.f) sidx[base++] = (unsigned short)(b0 + 0);
    if (v.y > 0.f) sidx[base++] = (unsigned short)(b0 + 1);
    if (v.z > 0.f) sidx[base++] = (unsigned short)(b0 + 2);
    if (v.w > 0.f) sidx[base++] = (unsigned short)(b0 + 3);
  }
  __syncthreads();

  if (nnz == 0) {
    float acc = 0.f;
    for (int n = 0; n < NSRC; n++) acc += transformed[(size_t)n * TFD + t];
    out[(size_t)m * TFD + t] = acc * (1.0f / NSRC);
    return;
  }

  // phase 1: exp(elu(score)) for both heads; cache + accumulate Z
  float pZ0 = 0.f, pZ1 = 0.f;
  for (int j = warp; j < nnz; j += 8) {
    float2 e = score_exp_pair(sidx[j], qsh, hsrc, lane);
    pZ0 += e.x; pZ1 += e.y;
    if (lane == 0 && j < ECAP) ecache[j] = e;
  }
  if (lane == 0) { red[warp] = pZ0; red[8 + warp] = pZ1; }
  __syncthreads();
  if (t == 0) {
    float z0 = 0.f, z1 = 0.f;
    #pragma unroll
    for (int wi = 0; wi < 8; wi++) { z0 += red[wi]; z1 += red[8 + wi]; }
    sZ0 = z0; sZ1 = z1;
  }
  __syncthreads();
  const float inv0 = 0.5f / sZ0;
  const float inv1 = 0.5f / sZ1;

  // combined weights from cache
  const int lim = min(nnz, ECAP);
  for (int j = t; j < lim; j += 256) {
    float2 e = ecache[j];
    scw[j] = e.x * inv0 + e.y * inv1;
  }
  __syncthreads();

  // gather-accumulate
  float acc = 0.f;
  #pragma unroll 4
  for (int j = 0; j < lim; j++)
    acc += scw[j] * transformed[(size_t)sidx[j] * TFD + t];

  // overflow remainder (practically never taken; kept for correctness)
  for (int c0 = ECAP; c0 < nnz; c0 += ECAP) {
    __syncthreads();
    int cend = min(nnz, c0 + ECAP);
    for (int j = c0 + warp; j < cend; j += 8) {
      float2 e = score_exp_pair(sidx[j], qsh, hsrc, lane);
      if (lane == 0) scw[j - c0] = e.x * inv0 + e.y * inv1;
    }
    __syncthreads();
    int cs = cend - c0;
    for (int j = 0; j < cs; j++)
      acc += scw[j] * transformed[(size_t)sidx[c0 + j] * TFD + t];
  }
  out[(size_t)m * TFD + t] = acc;
}

// ---------------------------------------------------------------------------
extern "C" void kernel_launch(void* const* d_in, const int* in_sizes, int n_in,
                              void* d_out, int out_size)
{
  const float* bias        = (const float*)d_in[0];
  const float* emb_dest    = (const float*)d_in[1];
  const float* emb_src     = (const float*)d_in[2];
  const float* feature_src = (const float*)d_in[3];
  const float* fc_W        = (const float*)d_in[4];
  const float* fc_b        = (const float*)d_in[5];
  const float* dec_W       = (const float*)d_in[6];
  const float* dec_b       = (const float*)d_in[7];
  const float* att_W       = (const float*)d_in[8];
  const float* att_W2      = (const float*)d_in[9];

  float* out_re  = (float*)d_out;
  float* out_hat = out_re + (size_t)NDEST * TFD;

  float *transformed, *hsrc, *qp, *wc;
  cudaGetSymbolAddress((void**)&transformed, g_transformed);
  cudaGetSymbolAddress((void**)&hsrc, g_hsrc);
  cudaGetSymbolAddress((void**)&qp, g_q);
  cudaGetSymbolAddress((void**)&wc, g_wc);

  // Wc[h] = att_W[h] @ att_W2[h]
  wc_kernel<<<dim3(32, 2), 256>>>(att_W, att_W2, wc);

  // h_src[h] = emb_src @ att_W[h]
  sgemm_k<<<dim3(HID / 64, NSRC / 64, HEADS), 256>>>(
      emb_src, att_W, hsrc, NSRC, HID, EMB,
      (long long)EMB * HID, (long long)NSRC * HID);

  // q[h] = emb_dest @ Wc[h]
  sgemm_k<<<dim3(HID / 64, NDEST / 64, HEADS), 256>>>(
      emb_dest, wc, qp, NDEST, HID, EMB,
      (long long)EMB * HID, (long long)NDEST * HID);

  // transformed = feature_src @ fc_W^T + fc_b   (tf32 tensor cores)
  tf32gemm_k<<<dim3(TFD / 64, NSRC / 128), 256>>>(
      feature_src, fc_W, fc_b, transformed, NSRC, TFD, FEATD);

  // feature_hat = transformed @ dec_W^T + dec_b (tf32 tensor cores)
  tf32gemm_k<<<dim3(FEATD / 64, NSRC / 128), 256>>>(
      transformed, dec_W, dec_b, out_hat, NSRC, FEATD, TFD);

  // sparse masked attention + aggregation
  attn_kernel<<<NDEST, 256>>>(bias, qp, hsrc, transformed, out_re);
}

// round 5
// speedup vs baseline: 1.6968x; 1.1020x over previous
#include <cuda_runtime.h>
#include <math.h>
#include <stdint.h>

#define NDEST 8192
#define NSRC  8192
#define FEATD 1024
#define TFD   256
#define EMB   64
#define HID   128
#define HEADS 2

// scratch (static device arrays: allocation-free)
__device__ float g_transformed[(size_t)NSRC * TFD];          // 8 MB
__device__ float g_hsrc[(size_t)HEADS * NSRC * HID];         // 8 MB
__device__ float g_q[(size_t)HEADS * NDEST * HID];           // 8 MB
__device__ float g_wc[HEADS * EMB * HID];                    // 64 KB

// ===========================================================================
// TF32 tensor-core GEMM:  C[M,N] = A[M,K] @ B[N,K]^T (+ bias[N])
// BM=128, BN=64, BK=32, 256 threads (8 warps as 4m x 2n, warp tile 32x32).
// Double-buffered smem (dynamic, 60KB) + register prefetch: ONE barrier per
// k-tile. k-permuted smem layout -> every mma fragment load is one
// conflict-free LDS.64 (row stride 40 words).
// ===========================================================================
__device__ __forceinline__ uint32_t f2tf(float f) {
  uint32_t u;
  asm("cvt.rna.tf32.f32 %0, %1;" : "=r"(u) : "f"(f));
  return u;
}

// store 8 k-consecutive values permuted: offsets (2j)->k=j, (2j+1)->k=j+4
__device__ __forceinline__ void store_perm(uint32_t* p, float4 lo, float4 hi) {
  uint4 u0 = make_uint4(f2tf(lo.x), f2tf(hi.x), f2tf(lo.y), f2tf(hi.y));
  uint4 u1 = make_uint4(f2tf(lo.z), f2tf(hi.z), f2tf(lo.w), f2tf(hi.w));
  *(uint4*)p = u0;
  *(uint4*)(p + 4) = u1;
}

__device__ __forceinline__ void mma_tf32(float* d, const uint32_t* a, uint2 b) {
  asm volatile(
      "mma.sync.aligned.m16n8k8.row.col.f32.tf32.tf32.f32 "
      "{%0,%1,%2,%3}, {%4,%5,%6,%7}, {%8,%9}, {%0,%1,%2,%3};\n"
      : "+f"(d[0]), "+f"(d[1]), "+f"(d[2]), "+f"(d[3])
      : "r"(a[0]), "r"(a[1]), "r"(a[2]), "r"(a[3]), "r"(b.x), "r"(b.y));
}

#define GEMM_SMEM_BYTES ((2 * 128 * 40 + 2 * 64 * 40) * 4)

__global__ __launch_bounds__(256, 2) void tf32gemm_k(
    const float* __restrict__ A, const float* __restrict__ B,
    const float* __restrict__ bias, float* __restrict__ C,
    int M, int N, int K)
{
  extern __shared__ uint32_t smdyn[];
  uint32_t (*Asm)[40] = (uint32_t(*)[40])smdyn;                 // 2 x 128 rows
  uint32_t (*Bsm)[40] = (uint32_t(*)[40])(smdyn + 2 * 128 * 40); // 2 x 64 rows

  const int t = threadIdx.x;
  const int lane = t & 31, w = t >> 5;
  const int wm = (w & 3) * 32;
  const int wn = (w >> 2) * 32;
  const int g = lane >> 2, c = lane & 3;

  const int row0 = blockIdx.y * 128;
  const int col0 = blockIdx.x * 64;

  const int lr = t >> 2;        // 0..63
  const int lk = (t & 3) * 8;   // 0,8,16,24

  const float* pA0 = A + (size_t)(row0 + lr) * K + lk;
  const float* pA1 = A + (size_t)(row0 + lr + 64) * K + lk;
  const float* pB  = B + (size_t)(col0 + lr) * K + lk;

  float4 a0lo = *(const float4*)(pA0);
  float4 a0hi = *(const float4*)(pA0 + 4);
  float4 a1lo = *(const float4*)(pA1);
  float4 a1hi = *(const float4*)(pA1 + 4);
  float4 blo  = *(const float4*)(pB);
  float4 bhi  = *(const float4*)(pB + 4);

  // prologue: fill stage 0
  store_perm(&Asm[lr][lk],      a0lo, a0hi);
  store_perm(&Asm[lr + 64][lk], a1lo, a1hi);
  store_perm(&Bsm[lr][lk],      blo,  bhi);
  __syncthreads();

  float acc[2][4][4] = {};
  int s = 0;

  for (int k0 = 0; k0 < K; k0 += 32) {
    const bool nxt = (k0 + 32 < K);
    if (nxt) {
      a0lo = *(const float4*)(pA0 + k0 + 32);
      a0hi = *(const float4*)(pA0 + k0 + 36);
      a1lo = *(const float4*)(pA1 + k0 + 32);
      a1hi = *(const float4*)(pA1 + k0 + 36);
      blo  = *(const float4*)(pB + k0 + 32);
      bhi  = *(const float4*)(pB + k0 + 36);
    }

    const uint32_t (*Ac)[40] = Asm + s * 128;
    const uint32_t (*Bc)[40] = Bsm + s * 64;

    #pragma unroll
    for (int ks = 0; ks < 4; ks++) {
      uint32_t af[2][4];
      uint2 bf[4];
      #pragma unroll
      for (int mi = 0; mi < 2; mi++) {
        uint2 lo = *(const uint2*)&Ac[wm + mi * 16 + g][ks * 8 + 2 * c];
        uint2 hi = *(const uint2*)&Ac[wm + mi * 16 + g + 8][ks * 8 + 2 * c];
        af[mi][0] = lo.x; af[mi][1] = hi.x; af[mi][2] = lo.y; af[mi][3] = hi.y;
      }
      #pragma unroll
      for (int ni = 0; ni < 4; ni++)
        bf[ni] = *(const uint2*)&Bc[wn + ni * 8 + g][ks * 8 + 2 * c];
      #pragma unroll
      for (int mi = 0; mi < 2; mi++)
        #pragma unroll
        for (int ni = 0; ni < 4; ni++)
          mma_tf32(acc[mi][ni], af[mi], bf[ni]);
    }

    if (nxt) {
      uint32_t (*An)[40] = Asm + (s ^ 1) * 128;
      uint32_t (*Bn)[40] = Bsm + (s ^ 1) * 64;
      store_perm(&An[lr][lk],      a0lo, a0hi);
      store_perm(&An[lr + 64][lk], a1lo, a1hi);
      store_perm(&Bn[lr][lk],      blo,  bhi);
      __syncthreads();
      s ^= 1;
    }
  }

  #pragma unroll
  for (int mi = 0; mi < 2; mi++) {
    int r = row0 + wm + mi * 16 + g;
    #pragma unroll
    for (int ni = 0; ni < 4; ni++) {
      int cc = col0 + wn + ni * 8 + 2 * c;
      float2 bv = *(const float2*)(bias + cc);
      float* d = acc[mi][ni];
      *(float2*)(C + (size_t)r * N + cc) =
          make_float2(d[0] + bv.x, d[1] + bv.y);
      *(float2*)(C + (size_t)(r + 8) * N + cc) =
          make_float2(d[2] + bv.x, d[3] + bv.y);
    }
  }
}

// ---------------------------------------------------------------------------
// fp32 SGEMM for the small score-path projections (kept fp32 for accuracy).
// ---------------------------------------------------------------------------
__global__ __launch_bounds__(256) void sgemm_k(
    const float* __restrict__ A, const float* __restrict__ B,
    float* __restrict__ C,
    int M, int N, int K, long long strideB, long long strideC)
{
  const float* Bp = B + (size_t)blockIdx.z * strideB;
  float* Cp = C + (size_t)blockIdx.z * strideC;

  __shared__ float As[16][68];
  __shared__ float Bs[16][68];

  const int t  = threadIdx.x;
  const int tx = t & 15;
  const int ty = t >> 4;
  const int row0 = blockIdx.y << 6;
  const int col0 = blockIdx.x << 6;

  const int aRow = t >> 2;
  const int aK   = (t & 3) << 2;
  const int bK   = t >> 4;
  const int bN   = (t & 15) << 2;

  float acc[4][4] = {};

  for (int k0 = 0; k0 < K; k0 += 16) {
    float4 a4 = *(const float4*)(A + (size_t)(row0 + aRow) * K + (k0 + aK));
    As[aK+0][aRow] = a4.x; As[aK+1][aRow] = a4.y;
    As[aK+2][aRow] = a4.z; As[aK+3][aRow] = a4.w;
    float4 b4 = *(const float4*)(Bp + (size_t)(k0 + bK) * N + (col0 + bN));
    *(float4*)&Bs[bK][bN] = b4;
    __syncthreads();
    #pragma unroll
    for (int k = 0; k < 16; k++) {
      float4 a = *(const float4*)&As[k][ty << 2];
      float4 b = *(const float4*)&Bs[k][tx << 2];
      acc[0][0] += a.x*b.x; acc[0][1] += a.x*b.y; acc[0][2] += a.x*b.z; acc[0][3] += a.x*b.w;
      acc[1][0] += a.y*b.x; acc[1][1] += a.y*b.y; acc[1][2] += a.y*b.z; acc[1][3] += a.y*b.w;
      acc[2][0] += a.z*b.x; acc[2][1] += a.z*b.y; acc[2][2] += a.z*b.z; acc[2][3] += a.z*b.w;
      acc[3][0] += a.w*b.x; acc[3][1] += a.w*b.y; acc[3][2] += a.w*b.z; acc[3][3] += a.w*b.w;
    }
    __syncthreads();
  }

  #pragma unroll
  for (int i = 0; i < 4; i++) {
    float4 o = make_float4(acc[i][0], acc[i][1], acc[i][2], acc[i][3]);
    *(float4*)(Cp + (size_t)(row0 + (ty<<2) + i) * N + (col0 + (tx<<2))) = o;
  }
}

// ---------------------------------------------------------------------------
// Wc[h] = att_W[h] (64x128) @ att_W2[h] (128x128)
// ---------------------------------------------------------------------------
__global__ void wc_kernel(const float* __restrict__ attW,
                          const float* __restrict__ attW2,
                          float* __restrict__ wc)
{
  int h = blockIdx.y;
  int idx = blockIdx.x * blockDim.x + threadIdx.x;
  int e = idx >> 7, d = idx & 127;
  const float* W  = attW  + h * EMB * HID + e * HID;
  const float* W2 = attW2 + h * HID * HID;
  float s = 0.f;
  #pragma unroll 8
  for (int k = 0; k < HID; k++) s += W[k] * W2[k * HID + d];
  wc[h * EMB * HID + idx] = s;
}

// ---------------------------------------------------------------------------
// Sparse masked attention, one block per destination row m.
// nnz ~ Binomial(8192, 0.01) = 82 +/- 9; buffers sized 2048 (~200 sigma).
// Chunked two-pass fallback keeps correctness for nnz > 2048 (never taken).
// ---------------------------------------------------------------------------
__device__ __forceinline__ float2 score_exp_pair(
    int n, const float* qsh, const float* __restrict__ hsrc, int lane)
{
  const float4* k0 = (const float4*)(hsrc + (size_t)n * HID);
  const float4* k1 = (const float4*)(hsrc + ((size_t)NSRC + n) * HID);
  const float4 a0 = ((const float4*)qsh)[lane];
  const float4 a1 = ((const float4*)qsh)[32 + lane];
  float4 b0 = k0[lane], b1 = k1[lane];
  float s0 = a0.x*b0.x + a0.y*b0.y + a0.z*b0.z + a0.w*b0.w;
  float s1 = a1.x*b1.x + a1.y*b1.y + a1.z*b1.z + a1.w*b1.w;
  #pragma unroll
  for (int o = 16; o; o >>= 1) {
    s0 += __shfl_xor_sync(0xffffffffu, s0, o);
    s1 += __shfl_xor_sync(0xffffffffu, s1, o);
  }
  float e0 = expf(s0 > 0.f ? s0 : expm1f(s0));  // exp(elu(s))
  float e1 = expf(s1 > 0.f ? s1 : expm1f(s1));
  return make_float2(e0, e1);
}

#define SCAP 2048
#define ECAP 1024

// compact nonzeros of bias[m, c0:c0+SCAP) into sidx; returns count.
__device__ __forceinline__ int compact_chunk(
    const float4* brow4, int c0, unsigned short* sidx,
    int t, int lane, int warp, int* s_warp)
{
  __syncthreads();  // protect sidx / s_warp reuse
  float4 v0 = brow4[c0 / 4 + t * 2];
  float4 v1 = brow4[c0 / 4 + t * 2 + 1];
  int cnt = (v0.x>0.f)+(v0.y>0.f)+(v0.z>0.f)+(v0.w>0.f)
          + (v1.x>0.f)+(v1.y>0.f)+(v1.z>0.f)+(v1.w>0.f);
  int inc = cnt;
  #pragma unroll
  for (int o = 1; o < 32; o <<= 1) {
    int u = __shfl_up_sync(0xffffffffu, inc, o);
    if (lane >= o) inc += u;
  }
  if (lane == 31) s_warp[warp] = inc;
  __syncthreads();
  int cn = 0, woff = 0;
  #pragma unroll
  for (int i = 0; i < 8; i++) {
    int u = s_warp[i];
    cn += u;
    if (i < warp) woff += u;
  }
  int base = woff + inc - cnt;
  int b0 = c0 + t * 8;
  if (v0.x > 0.f) sidx[base++] = (unsigned short)(b0 + 0);
  if (v0.y > 0.f) sidx[base++] = (unsigned short)(b0 + 1);
  if (v0.z > 0.f) sidx[base++] = (unsigned short)(b0 + 2);
  if (v0.w > 0.f) sidx[base++] = (unsigned short)(b0 + 3);
  if (v1.x > 0.f) sidx[base++] = (unsigned short)(b0 + 4);
  if (v1.y > 0.f) sidx[base++] = (unsigned short)(b0 + 5);
  if (v1.z > 0.f) sidx[base++] = (unsigned short)(b0 + 6);
  if (v1.w > 0.f) sidx[base++] = (unsigned short)(b0 + 7);
  __syncthreads();
  return cn;
}

__global__ __launch_bounds__(256) void attn_kernel(
    const float* __restrict__ bias,
    const float* __restrict__ q,            // [2][NDEST][HID]
    const float* __restrict__ hsrc,         // [2][NSRC][HID]
    const float* __restrict__ transformed,  // [NSRC][TFD]
    float* __restrict__ out)                // [NDEST][TFD]
{
  const int m = blockIdx.x;
  const int t = threadIdx.x;
  const int warp = t >> 5, lane = t & 31;

  __shared__ unsigned short sidx[SCAP];        // 4 KB
  __shared__ __align__(16) float qsh[2 * HID]; // 1 KB
  __shared__ float2 ecache[ECAP];              // 8 KB
  __shared__ float scw[SCAP];                  // 8 KB
  __shared__ int s_warp[8];
  __shared__ float red[16];
  __shared__ float sZ0, sZ1;

  {
    int h = t >> 7, d = t & 127;
    qsh[t] = q[((size_t)h * NDEST + m) * HID + d];
  }

  const float4* brow4 = (const float4*)(bias + (size_t)m * NSRC);

  // count nonzeros in this thread's 32 columns; warp-shuffle scan
  float4 v[8];
  int cnt = 0;
  #pragma unroll
  for (int i = 0; i < 8; i++) {
    v[i] = brow4[t * 8 + i];
    cnt += (v[i].x>0.f)+(v[i].y>0.f)+(v[i].z>0.f)+(v[i].w>0.f);
  }
  int inc = cnt;
  #pragma unroll
  for (int o = 1; o < 32; o <<= 1) {
    int u = __shfl_up_sync(0xffffffffu, inc, o);
    if (lane >= o) inc += u;
  }
  if (lane == 31) s_warp[warp] = inc;
  __syncthreads();
  int nnz = 0, woff = 0;
  #pragma unroll
  for (int i = 0; i < 8; i++) {
    int u = s_warp[i];
    nnz += u;
    if (i < warp) woff += u;
  }

  if (nnz == 0) {
    // all masked: softmax uniform over all sources (reference behavior)
    float acc = 0.f;
    for (int n = 0; n < NSRC; n++) acc += transformed[(size_t)n * TFD + t];
    out[(size_t)m * TFD + t] = acc * (1.0f / NSRC);
    return;
  }

  if (nnz <= SCAP) {
    // ---------------- fast path ----------------
    int base = woff + inc - cnt;
    #pragma unroll
    for (int i = 0; i < 8; i++) {
      int b0 = t * 32 + i * 4;
      if (v[i].x > 0.f) sidx[base++] = (unsigned short)(b0 + 0);
      if (v[i].y > 0.f) sidx[base++] = (unsigned short)(b0 + 1);
      if (v[i].z > 0.f) sidx[base++] = (unsigned short)(b0 + 2);
      if (v[i].w > 0.f) sidx[base++] = (unsigned short)(b0 + 3);
    }
    __syncthreads();

    // phase 1: exp(elu(score)), cache, accumulate Z
    float pZ0 = 0.f, pZ1 = 0.f;
    for (int j = warp; j < nnz; j += 8) {
      float2 e = score_exp_pair(sidx[j], qsh, hsrc, lane);
      pZ0 += e.x; pZ1 += e.y;
      if (lane == 0 && j < ECAP) ecache[j] = e;
    }
    if (lane == 0) { red[warp] = pZ0; red[8 + warp] = pZ1; }
    __syncthreads();
    if (t == 0) {
      float z0 = 0.f, z1 = 0.f;
      #pragma unroll
      for (int wi = 0; wi < 8; wi++) { z0 += red[wi]; z1 += red[8 + wi]; }
      sZ0 = z0; sZ1 = z1;
    }
    __syncthreads();
    const float inv0 = 0.5f / sZ0;
    const float inv1 = 0.5f / sZ1;

    // weights: cached part + (never-taken) recompute tail
    const int clim = min(nnz, ECAP);
    for (int j = t; j < clim; j += 256) {
      float2 e = ecache[j];
      scw[j] = e.x * inv0 + e.y * inv1;
    }
    for (int j = ECAP + warp; j < nnz; j += 8) {
      float2 e = score_exp_pair(sidx[j], qsh, hsrc, lane);
      if (lane == 0) scw[j] = e.x * inv0 + e.y * inv1;
    }
    __syncthreads();

    // gather-accumulate, 8-wide for MLP
    float acc = 0.f;
    int j = 0;
    for (; j + 8 <= nnz; j += 8) {
      float w0=scw[j+0], w1=scw[j+1], w2=scw[j+2], w3=scw[j+3];
      float w4=scw[j+4], w5=scw[j+5], w6=scw[j+6], w7=scw[j+7];
      float x0 = transformed[(size_t)sidx[j+0] * TFD + t];
      float x1 = transformed[(size_t)sidx[j+1] * TFD + t];
      float x2 = transformed[(size_t)sidx[j+2] * TFD + t];
      float x3 = transformed[(size_t)sidx[j+3] * TFD + t];
      float x4 = transformed[(size_t)sidx[j+4] * TFD + t];
      float x5 = transformed[(size_t)sidx[j+5] * TFD + t];
      float x6 = transformed[(size_t)sidx[j+6] * TFD + t];
      float x7 = transformed[(size_t)sidx[j+7] * TFD + t];
      acc += w0*x0 + w1*x1 + w2*x2 + w3*x3 + w4*x4 + w5*x5 + w6*x6 + w7*x7;
    }
    for (; j < nnz; j++)
      acc += scw[j] * transformed[(size_t)sidx[j] * TFD + t];
    out[(size_t)m * TFD + t] = acc;
    return;
  }

  // -------- fallback: nnz > SCAP, chunked two-pass (never expected) --------
  float pZ0 = 0.f, pZ1 = 0.f;
  for (int c0 = 0; c0 < NSRC; c0 += SCAP) {
    int cn = compact_chunk(brow4, c0, sidx, t, lane, warp, s_warp);
    for (int j = warp; j < cn; j += 8) {
      float2 e = score_exp_pair(sidx[j], qsh, hsrc, lane);
      pZ0 += e.x; pZ1 += e.y;
    }
  }
  if (lane == 0) { red[warp] = pZ0; red[8 + warp] = pZ1; }
  __syncthreads();
  if (t == 0) {
    float z0 = 0.f, z1 = 0.f;
    #pragma unroll
    for (int wi = 0; wi < 8; wi++) { z0 += red[wi]; z1 += red[8 + wi]; }
    sZ0 = z0; sZ1 = z1;
  }
  __syncthreads();
  const float inv0 = 0.5f / sZ0;
  const float inv1 = 0.5f / sZ1;

  float acc = 0.f;
  for (int c0 = 0; c0 < NSRC; c0 += SCAP) {
    int cn = compact_chunk(brow4, c0, sidx, t, lane, warp, s_warp);
    for (int j = warp; j < cn; j += 8) {
      float2 e = score_exp_pair(sidx[j], qsh, hsrc, lane);
      if (lane == 0) scw[j] = e.x * inv0 + e.y * inv1;
    }
    __syncthreads();
    for (int j = 0; j < cn; j++)
      acc += scw[j] * transformed[(size_t)sidx[j] * TFD + t];
  }
  out[(size_t)m * TFD + t] = acc;
}

// ---------------------------------------------------------------------------
extern "C" void kernel_launch(void* const* d_in, const int* in_sizes, int n_in,
                              void* d_out, int out_size)
{
  const float* bias        = (const float*)d_in[0];
  const float* emb_dest    = (const float*)d_in[1];
  const float* emb_src     = (const float*)d_in[2];
  const float* feature_src = (const float*)d_in[3];
  const float* fc_W        = (const float*)d_in[4];
  const float* fc_b        = (const float*)d_in[5];
  const float* dec_W       = (const float*)d_in[6];
  const float* dec_b       = (const float*)d_in[7];
  const float* att_W       = (const float*)d_in[8];
  const float* att_W2      = (const float*)d_in[9];

  float* out_re  = (float*)d_out;
  float* out_hat = out_re + (size_t)NDEST * TFD;

  float *transformed, *hsrc, *qp, *wc;
  cudaGetSymbolAddress((void**)&transformed, g_transformed);
  cudaGetSymbolAddress((void**)&hsrc, g_hsrc);
  cudaGetSymbolAddress((void**)&qp, g_q);
  cudaGetSymbolAddress((void**)&wc, g_wc);

  cudaFuncSetAttribute(tf32gemm_k,
                       cudaFuncAttributeMaxDynamicSharedMemorySize,
                       GEMM_SMEM_BYTES);

  // Wc[h] = att_W[h] @ att_W2[h]
  wc_kernel<<<dim3(32, 2), 256>>>(att_W, att_W2, wc);

  // h_src[h] = emb_src @ att_W[h]
  sgemm_k<<<dim3(HID / 64, NSRC / 64, HEADS), 256>>>(
      emb_src, att_W, hsrc, NSRC, HID, EMB,
      (long long)EMB * HID, (long long)NSRC * HID);

  // q[h] = emb_dest @ Wc[h]
  sgemm_k<<<dim3(HID / 64, NDEST / 64, HEADS), 256>>>(
      emb_dest, wc, qp, NDEST, HID, EMB,
      (long long)EMB * HID, (long long)NDEST * HID);

  // transformed = feature_src @ fc_W^T + fc_b   (tf32 tensor cores)
  tf32gemm_k<<<dim3(TFD / 64, NSRC / 128), 256, GEMM_SMEM_BYTES>>>(
      feature_src, fc_W, fc_b, transformed, NSRC, TFD, FEATD);

  // feature_hat = transformed @ dec_W^T + dec_b (tf32 tensor cores)
  tf32gemm_k<<<dim3(FEATD / 64, NSRC / 128), 256, GEMM_SMEM_BYTES>>>(
      transformed, dec_W, dec_b, out_hat, NSRC, FEATD, TFD);

  // sparse masked attention + aggregation
  attn_kernel<<<NDEST, 256>>>(bias, qp, hsrc, transformed, out_re);
}